// round 15
// baseline (speedup 1.0000x reference)
#include <cuda_runtime.h>
#include <cuda_bf16.h>
#include <cuda_fp16.h>
#include <cstdint>

#define MOLS 128
#define L 256
#define H 768
#define NH 12
#define HD 64
#define NROWS (MOLS * L)
#define NRH ((size_t)NROWS * H)
#define SCALE2 0.1803368801111204f   /* HD^-0.5 * log2(e) */

// ---- GEMM tiling (pure fp16 single-term, BK=96, double buffer) ----
#define BM 128
#define BN 128
#define BK 96
#define KSTG (H / BK)        // 8
#define ROWB 208             // 96 fp16 = 192B data + 16B pad (208%128==80: conflict-free)
#define TILE_A (BM * ROWB)   // 26624
#define STAGE_BYTES (2 * TILE_A)           // A, B = 53248
#define GEMM_SMEM (2 * STAGE_BYTES)        // 106496  (x2 CTAs/SM = 212992 <= 228K)

// ---- attention smem layout (bytes), single fp16 K and V^T ----
#define ATT_K 0                            // 256 rows * 144
#define ATT_V 36864                        // 64 rows * 528
#define ATT_SMEM 70656
#define ATT_THREADS 512

// ---------------- scratch (device globals) ---------------------------------
__device__ __half g_Xh[NRH];                 // masked input, fp16
__device__ __half g_Ch[NRH];                 // attention ctx, fp16
__device__ __half g_Wh[4][(size_t)H * H];    // weights fp16 (Wq pre-scaled)
__device__ __half g_PRJ[3 * NRH];            // Q | K | V  (fp16)
__device__ float g_Cf[NRH];                  // O-projection output (fp32)

// ---------------- helpers ---------------------------------------------------
__device__ __forceinline__ uint32_t smem_u32(const void* p) {
    uint32_t a;
    asm("{ .reg .u64 t; cvta.to.shared.u64 t, %1; cvt.u32.u64 %0, t; }"
        : "=r"(a) : "l"(p));
    return a;
}
__device__ __forceinline__ float ex2(float x) {
    float y;
    asm("ex2.approx.ftz.f32 %0, %1;" : "=f"(y) : "f"(x));
    return y;
}
__device__ __forceinline__ void cp16(uint32_t s, const void* g) {
    asm volatile("cp.async.cg.shared.global [%0], [%1], 16;" :: "r"(s), "l"(g));
}
#define CP_COMMIT() asm volatile("cp.async.commit_group;" ::: "memory")
#define CP_WAIT0()  asm volatile("cp.async.wait_group 0;" ::: "memory")
#define LDM4(r0, r1, r2, r3, addr) \
    asm volatile("ldmatrix.sync.aligned.m8n8.x4.shared.b16 {%0,%1,%2,%3}, [%4];" \
                 : "=r"(r0), "=r"(r1), "=r"(r2), "=r"(r3) : "r"(addr))
__device__ __forceinline__ void mma_f16(float d[4], const uint32_t a[4],
                                        uint32_t b0, uint32_t b1) {
    asm volatile(
        "mma.sync.aligned.m16n8k16.row.col.f32.f16.f16.f32 "
        "{%0,%1,%2,%3}, {%4,%5,%6,%7}, {%8,%9}, {%0,%1,%2,%3};\n"
        : "+f"(d[0]), "+f"(d[1]), "+f"(d[2]), "+f"(d[3])
        : "r"(a[0]), "r"(a[1]), "r"(a[2]), "r"(a[3]), "r"(b0), "r"(b1));
}

// ---------------- masked gather -> fp16 --------------------------------------
__global__ void build_x_kernel(const float* __restrict__ atom,
                               const int* __restrict__ a_starts,
                               const int* __restrict__ a_sizes) {
    int i = blockIdx.x * blockDim.x + threadIdx.x;     // float4 index
    const int W4 = H / 4;
    int row = i / W4;
    int c4  = (i - row * W4) * 4;
    int m = row / L;
    int l = row - m * L;
    float4 val = make_float4(0.f, 0.f, 0.f, 0.f);
    if (l < a_sizes[m]) {
        int src = a_starts[m] + l;
        val = *(const float4*)&atom[(size_t)src * H + c4];
    }
    __half2 h0 = __float22half2_rn(make_float2(val.x, val.y));
    __half2 h1 = __float22half2_rn(make_float2(val.z, val.w));
    uint2 o;
    o.x = *(uint32_t*)&h0;
    o.y = *(uint32_t*)&h1;
    *(uint2*)&g_Xh[(size_t)row * H + c4] = o;
}

// ---------------- all 4 weights fp32 -> fp16 (Wq pre-scaled) ----------------
__global__ void cvt_w_kernel(const float* __restrict__ W0, const float* __restrict__ W1,
                             const float* __restrict__ W2, const float* __restrict__ W3) {
    int i = blockIdx.x * blockDim.x + threadIdx.x;     // float4 idx over 4*H*H
    const int PW = H * H / 4;
    int slab = i / PW;
    int j = i - slab * PW;
    const float* W = (slab == 0) ? W0 : (slab == 1) ? W1 : (slab == 2) ? W2 : W3;
    float sc = (slab == 0) ? SCALE2 : 1.f;
    float4 v = ((const float4*)W)[j];
    __half2 h0 = __float22half2_rn(make_float2(v.x * sc, v.y * sc));
    __half2 h1 = __float22half2_rn(make_float2(v.z * sc, v.w * sc));
    uint2 o;
    o.x = *(uint32_t*)&h0;
    o.y = *(uint32_t*)&h1;
    ((uint2*)&g_Wh[0][0])[i] = o;
}

// ---------------- fp16 GEMM: C[n,o] = A·Bᵗ + bias ---------------------------
// BK=96, 8 stages, distance-1 double buffer (wait(ks)->sync->issue(ks+1)->compute).
// Row-validity skip; identical k16-chunk accumulation order as before.
template <bool SPLIT>
__global__ __launch_bounds__(256, 2) void gemm_f16_kernel(
    const __half* __restrict__ Ag, const __half* __restrict__ Bg,
    const float* __restrict__ b0, const float* __restrict__ b1,
    const float* __restrict__ b2, float* __restrict__ Cf,
    __half* __restrict__ Dh, const int* __restrict__ asz) {
    extern __shared__ char sm[];
    const uint32_t smb = smem_u32(sm);
    const int tid = threadIdx.x;
    const int lane = tid & 31;
    const int wid = tid >> 5;
    const int wm = wid >> 2;            // 0..1
    const int wn = wid & 3;             // 0..3
    const int bm = blockIdx.y * BM;
    const int bn = blockIdx.x * BN;

    // valid rows in this tile: molecule = blockIdx.y>>1, tile offset 0 or 128
    const int vt = asz[blockIdx.y >> 1] - ((blockIdx.y & 1) << 7);
    const int nmt = max(0, min(4, (vt - wm * 64 + 15) >> 4));   // valid subtiles

    float acc[4][4][4];
#pragma unroll
    for (int i = 0; i < 4; i++)
#pragma unroll
        for (int j = 0; j < 4; j++)
#pragma unroll
            for (int t = 0; t < 4; t++) acc[i][j][t] = 0.f;

    // 1536 16B chunks per tile (128 rows x 12 chunks); 6 per thread per tile
    auto load_stage = [&](int buf, int k0) {
        uint32_t sb = smb + buf * STAGE_BYTES;
#pragma unroll
        for (int i = 0; i < 6; i++) {
            int c = tid + i * 256;
            int row = c / 12, kc = c - row * 12;
            uint32_t so = row * ROWB + kc * 16;
            size_t go = (size_t)row * H + k0 + kc * 8;
            cp16(sb + so, Ag + (size_t)bm * H + go);
            cp16(sb + TILE_A + so, Bg + (size_t)bn * H + go);
        }
    };

    load_stage(0, 0);
    CP_COMMIT();

    const int trow = lane & 15;
    const int tkb = (lane >> 4) * 16;

#pragma unroll 1
    for (int ks = 0; ks < KSTG; ks++) {
        CP_WAIT0();                       // stage ks landed (ks+1 not yet issued)
        __syncthreads();                  // all warps done reading buffer (ks+1)&1
        if (ks + 1 < KSTG) {
            load_stage((ks + 1) & 1, (ks + 1) * BK);
            CP_COMMIT();
        }

        const uint32_t sA = smb + (ks & 1) * STAGE_BYTES;
        const uint32_t sB = sA + TILE_A;
        if (nmt > 0) {
#pragma unroll
            for (int kh = 0; kh < 6; kh++) {      // 96 = 6 x 16-k chunks
                const uint32_t koff = kh * 32 + tkb;
                uint32_t av[4][4], bv[2][4];
#pragma unroll
                for (int mt = 0; mt < 4; mt++) {
                    if (mt < nmt) {
                        uint32_t a = sA + (wm * 64 + mt * 16 + trow) * ROWB + koff;
                        LDM4(av[mt][0], av[mt][1], av[mt][2], av[mt][3], a);
                    }
                }
#pragma unroll
                for (int g = 0; g < 2; g++) {
                    uint32_t b = sB + (wn * 32 + g * 16 + trow) * ROWB + koff;
                    LDM4(bv[g][0], bv[g][1], bv[g][2], bv[g][3], b);
                }
#pragma unroll
                for (int mt = 0; mt < 4; mt++) {
                    if (mt < nmt) {
#pragma unroll
                        for (int nt = 0; nt < 4; nt++) {
                            const int g = nt >> 1, s = nt & 1;
                            mma_f16(acc[mt][nt], av[mt], bv[g][s], bv[g][s + 2]);
                        }
                    }
                }
            }
        }
    }

    if (SPLIT) {
        const int sect = blockIdx.x / 6;                 // 0=Q 1=K 2=V
        const int coff = bn - sect * 768;
        const float* bias = (sect == 0) ? b0 : (sect == 1) ? b1 : b2;
        const float bscale = (sect == 0) ? SCALE2 : 1.f;
        __half* dh = Dh + (size_t)sect * NRH;
#pragma unroll
        for (int mt = 0; mt < 4; mt++) {
            if (mt >= nmt) continue;
            int row = bm + wm * 64 + mt * 16 + (lane >> 2);
#pragma unroll
            for (int nt = 0; nt < 4; nt++) {
                int cl = coff + wn * 32 + nt * 8 + (lane & 3) * 2;
                float bb0 = bias[cl] * bscale, bb1 = bias[cl + 1] * bscale;
                size_t o = (size_t)row * H + cl;
                __half2 v0 = __float22half2_rn(
                    make_float2(acc[mt][nt][0] + bb0, acc[mt][nt][1] + bb1));
                __half2 v1 = __float22half2_rn(
                    make_float2(acc[mt][nt][2] + bb0, acc[mt][nt][3] + bb1));
                *(uint32_t*)&dh[o] = *(uint32_t*)&v0;
                *(uint32_t*)&dh[o + 8 * H] = *(uint32_t*)&v1;
            }
        }
    } else {
#pragma unroll
        for (int mt = 0; mt < 4; mt++) {
            if (mt >= nmt) continue;
            int row = bm + wm * 64 + mt * 16 + (lane >> 2);
#pragma unroll
            for (int nt = 0; nt < 4; nt++) {
                int col = bn + wn * 32 + nt * 8 + (lane & 3) * 2;
                float2 bb = *(const float2*)&b0[col];
                float* p = Cf + (size_t)row * H + col;
                *(float2*)p = make_float2(acc[mt][nt][0] + bb.x, acc[mt][nt][1] + bb.y);
                *(float2*)(p + 8 * H) =
                    make_float2(acc[mt][nt][2] + bb.x, acc[mt][nt][3] + bb.y);
            }
        }
    }
}

// ---------------- tensor-core flash attention (single fp16) -----------------
// One 512-thread CTA per (head, molecule): K/V staged ONCE; warp w handles
// q rows [w*16, w*16+16); warps entirely in padding exit after staging.
__global__ __launch_bounds__(ATT_THREADS, 1) void attn_tc_kernel(
    const int* __restrict__ a_sizes) {
    extern __shared__ char sm[];
    const uint32_t smb = smem_u32(sm);
    const int h = blockIdx.x, m = blockIdx.y;
    const int tid = threadIdx.x;
    const int lane = tid & 31;
    const int wid = tid >> 5;
    const int size = a_sizes[m];

    const __half* Qh = g_PRJ;
    const __half* Kh = g_PRJ + NRH;
    const __half* Vh = g_PRJ + 2 * NRH;

    // ---- stage K (row-major, pitch 144B): pure 16B copies ----
#pragma unroll
    for (int it = 0; it < 4; it++) {
        int i = tid + it * ATT_THREADS;
        int row = i >> 3, ch = (i & 7) * 8;
        size_t src = (size_t)(m * L + row) * H + h * HD + ch;
        *(uint4*)(sm + ATT_K + row * 144 + ch * 2) = *(const uint4*)&Kh[src];
    }
    // ---- stage V^T (pitch 528B): transpose via 2B reads ----
#pragma unroll
    for (int it = 0; it < 16; it++) {
        int p = tid + it * ATT_THREADS;
        int d = p & 63, j = (p >> 6) * 2;
        size_t s0 = (size_t)(m * L + j) * H + h * HD + d;
        uint32_t v0 = *(const unsigned short*)&Vh[s0];
        uint32_t v1 = *(const unsigned short*)&Vh[s0 + H];
        *(uint32_t*)(sm + ATT_V + d * 528 + j * 2) = v0 | (v1 << 16);
    }
    __syncthreads();

    // warps fully in the padding region do no attention work
    if (wid * 16 >= size) return;

    const int tq2 = (lane & 3) * 2;
    const int l15 = lane & 15;
    const int lhk = (lane >> 4) * 16;
    const int row0 = wid * 16 + (lane >> 2);

    // Q fragments straight from gmem (already scaled, fp16)
    uint32_t qv[4][4];
    {
        const size_t qb = (size_t)(m * L + row0) * H + h * HD;
#pragma unroll
        for (int ks = 0; ks < 4; ks++) {
            int k = ks * 16 + tq2;
            qv[ks][0] = *(const uint32_t*)&Qh[qb + k];
            qv[ks][1] = *(const uint32_t*)&Qh[qb + 8 * H + k];
            qv[ks][2] = *(const uint32_t*)&Qh[qb + k + 8];
            qv[ks][3] = *(const uint32_t*)&Qh[qb + 8 * H + k + 8];
        }
    }

    float O[8][4];
#pragma unroll
    for (int i = 0; i < 8; i++)
#pragma unroll
        for (int j = 0; j < 4; j++) O[i][j] = 0.f;
    float m0 = -1e30f, m1 = -1e30f, l0 = 0.f, l1 = 0.f;

    const int nch = min(4, (size + 63) >> 6);
#pragma unroll 1
    for (int c = 0; c < nch; c++) {
        const int j0 = c * 64;
        float S[8][4];
#pragma unroll
        for (int i = 0; i < 8; i++)
#pragma unroll
            for (int j = 0; j < 4; j++) S[i][j] = 0.f;

        // ---- QK: S = Q'·K^T (log2 domain) ----
#pragma unroll
        for (int np = 0; np < 4; np++) {
            uint32_t kra = smb + ATT_K + (j0 + np * 16 + l15) * 144 + lhk;
#pragma unroll
            for (int ks = 0; ks < 4; ks++) {
                uint32_t k0, k1, k2, k3;
                LDM4(k0, k1, k2, k3, kra + ks * 32);
                mma_f16(S[2 * np], qv[ks], k0, k2);
                mma_f16(S[2 * np + 1], qv[ks], k1, k3);
            }
        }

        // ---- mask boundary chunk ----
        if (j0 + 64 > size) {
#pragma unroll
            for (int nt = 0; nt < 8; nt++) {
                int col = j0 + nt * 8 + tq2;
                if (col >= size)     { S[nt][0] = -1e30f; S[nt][2] = -1e30f; }
                if (col + 1 >= size) { S[nt][1] = -1e30f; S[nt][3] = -1e30f; }
            }
        }

        // ---- online softmax on fragments ----
        float mx0 = -1e30f, mx1 = -1e30f;
#pragma unroll
        for (int nt = 0; nt < 8; nt++) {
            mx0 = fmaxf(mx0, fmaxf(S[nt][0], S[nt][1]));
            mx1 = fmaxf(mx1, fmaxf(S[nt][2], S[nt][3]));
        }
        mx0 = fmaxf(mx0, __shfl_xor_sync(0xffffffffu, mx0, 1));
        mx0 = fmaxf(mx0, __shfl_xor_sync(0xffffffffu, mx0, 2));
        mx1 = fmaxf(mx1, __shfl_xor_sync(0xffffffffu, mx1, 1));
        mx1 = fmaxf(mx1, __shfl_xor_sync(0xffffffffu, mx1, 2));
        float nm0 = fmaxf(m0, mx0), nm1 = fmaxf(m1, mx1);
        float f0 = ex2(m0 - nm0), f1 = ex2(m1 - nm1);
        float rs0 = 0.f, rs1 = 0.f;
#pragma unroll
        for (int nt = 0; nt < 8; nt++) {
            S[nt][0] = ex2(S[nt][0] - nm0); rs0 += S[nt][0];
            S[nt][1] = ex2(S[nt][1] - nm0); rs0 += S[nt][1];
            S[nt][2] = ex2(S[nt][2] - nm1); rs1 += S[nt][2];
            S[nt][3] = ex2(S[nt][3] - nm1); rs1 += S[nt][3];
        }
        rs0 += __shfl_xor_sync(0xffffffffu, rs0, 1);
        rs0 += __shfl_xor_sync(0xffffffffu, rs0, 2);
        rs1 += __shfl_xor_sync(0xffffffffu, rs1, 1);
        rs1 += __shfl_xor_sync(0xffffffffu, rs1, 2);
        l0 = l0 * f0 + rs0;
        l1 = l1 * f1 + rs1;
        m0 = nm0; m1 = nm1;
#pragma unroll
        for (int dt = 0; dt < 8; dt++) {
            O[dt][0] *= f0; O[dt][1] *= f0;
            O[dt][2] *= f1; O[dt][3] *= f1;
        }

        // ---- P fragments (single fp16) ----
        uint32_t pv[4][4];
#pragma unroll
        for (int ks = 0; ks < 4; ks++) {
            __half2 p0 = __float22half2_rn(make_float2(S[2 * ks][0], S[2 * ks][1]));
            __half2 p1 = __float22half2_rn(make_float2(S[2 * ks][2], S[2 * ks][3]));
            __half2 p2 = __float22half2_rn(make_float2(S[2 * ks + 1][0], S[2 * ks + 1][1]));
            __half2 p3 = __float22half2_rn(make_float2(S[2 * ks + 1][2], S[2 * ks + 1][3]));
            pv[ks][0] = *(uint32_t*)&p0;
            pv[ks][1] = *(uint32_t*)&p1;
            pv[ks][2] = *(uint32_t*)&p2;
            pv[ks][3] = *(uint32_t*)&p3;
        }

        // ---- PV: O += P·V ----
#pragma unroll
        for (int dp = 0; dp < 4; dp++) {
            uint32_t vra = smb + ATT_V + (dp * 16 + l15) * 528 + j0 * 2 + lhk;
#pragma unroll
            for (int ks = 0; ks < 4; ks++) {
                uint32_t v0, v1, v2, v3;
                LDM4(v0, v1, v2, v3, vra + ks * 32);
                mma_f16(O[2 * dp], pv[ks], v0, v2);
                mma_f16(O[2 * dp + 1], pv[ks], v1, v3);
            }
        }
    }

    // ---- normalize + write ctx fp16 ----
    const float i0 = 1.f / l0, i1 = 1.f / l1;
    const size_t ob = (size_t)(m * L + row0) * H + h * HD + tq2;
#pragma unroll
    for (int dt = 0; dt < 8; dt++) {
        __half2 c0 = __float22half2_rn(make_float2(O[dt][0] * i0, O[dt][1] * i0));
        __half2 c1 = __float22half2_rn(make_float2(O[dt][2] * i1, O[dt][3] * i1));
        *(uint32_t*)&g_Ch[ob + dt * 8] = *(uint32_t*)&c0;
        *(uint32_t*)&g_Ch[ob + 8 * H + dt * 8] = *(uint32_t*)&c1;
    }
}

// -------- residual + LayerNorm + mask + scatter (covers ALL rows) ----------
__global__ __launch_bounds__(256) void ln_kernel(
    const float* __restrict__ atom,
    const float* __restrict__ gamma, const float* __restrict__ beta,
    const int* __restrict__ a_starts, const int* __restrict__ a_sizes,
    float* __restrict__ out) {
    const int row = blockIdx.x;
    const int m = row / L;
    const int l = row - m * L;
    const int tid = threadIdx.x;

    const bool valid = l < a_sizes[m];
    const int dst = a_starts[m] + l;

    if (!valid) {   // uniform across block: padding rows just write zeros
#pragma unroll
        for (int i = 0; i < 3; i++)
            out[(size_t)dst * H + tid + i * 256] = 0.f;
        return;
    }

    __shared__ float redbuf[8];
    __shared__ float stat[2];

    float y[3];
    float s = 0.f;
#pragma unroll
    for (int i = 0; i < 3; i++) {
        int col = tid + i * 256;
        float v = g_Cf[(size_t)row * H + col] + atom[(size_t)dst * H + col];
        y[i] = v;
        s += v;
    }
#pragma unroll
    for (int o = 16; o > 0; o >>= 1) s += __shfl_xor_sync(0xffffffffu, s, o);
    if ((tid & 31) == 0) redbuf[tid >> 5] = s;
    __syncthreads();
    if (tid == 0) {
        float t = 0.f;
#pragma unroll
        for (int i = 0; i < 8; i++) t += redbuf[i];
        stat[0] = t;
    }
    __syncthreads();
    const float mu = stat[0] * (1.f / 768.f);

    float vs = 0.f;
#pragma unroll
    for (int i = 0; i < 3; i++) {
        float d = y[i] - mu;
        vs += d * d;
    }
#pragma unroll
    for (int o = 16; o > 0; o >>= 1) vs += __shfl_xor_sync(0xffffffffu, vs, o);
    if ((tid & 31) == 0) redbuf[tid >> 5] = vs;
    __syncthreads();
    if (tid == 0) {
        float t = 0.f;
#pragma unroll
        for (int i = 0; i < 8; i++) t += redbuf[i];
        stat[1] = t;
    }
    __syncthreads();
    const float rstd = rsqrtf(stat[1] * (1.f / 768.f) + 1e-5f);

#pragma unroll
    for (int i = 0; i < 3; i++) {
        int col = tid + i * 256;
        out[(size_t)dst * H + col] = (y[i] - mu) * rstd * gamma[col] + beta[col];
    }
}

// ---------------------------------------------------------------------------
extern "C" void kernel_launch(void* const* d_in, const int* in_sizes, int n_in,
                              void* d_out, int out_size) {
    const float* atom     = (const float*)d_in[0];
    const float* Wq       = (const float*)d_in[1];
    const float* bq       = (const float*)d_in[2];
    const float* Wk       = (const float*)d_in[3];
    const float* bk       = (const float*)d_in[4];
    const float* Wv       = (const float*)d_in[5];
    const float* bv       = (const float*)d_in[6];
    const float* Wo       = (const float*)d_in[7];
    const float* bo       = (const float*)d_in[8];
    const float* gamma    = (const float*)d_in[9];
    const float* beta     = (const float*)d_in[10];
    const int*   a_starts = (const int*)d_in[11];
    const int*   a_sizes  = (const int*)d_in[12];
    float* out = (float*)d_out;

    __half *pXh, *pCh, *pWh, *pP;
    float* pCf;
    cudaGetSymbolAddress((void**)&pXh, g_Xh);
    cudaGetSymbolAddress((void**)&pCh, g_Ch);
    cudaGetSymbolAddress((void**)&pWh, g_Wh);
    cudaGetSymbolAddress((void**)&pP, g_PRJ);
    cudaGetSymbolAddress((void**)&pCf, g_Cf);
    const size_t WSZ = (size_t)H * H;

    cudaFuncSetAttribute(attn_tc_kernel, cudaFuncAttributeMaxDynamicSharedMemorySize,
                         ATT_SMEM);
    cudaFuncSetAttribute(gemm_f16_kernel<true>,
                         cudaFuncAttributeMaxDynamicSharedMemorySize, GEMM_SMEM);
    cudaFuncSetAttribute(gemm_f16_kernel<false>,
                         cudaFuncAttributeMaxDynamicSharedMemorySize, GEMM_SMEM);

    build_x_kernel<<<(NROWS * H / 4) / 256, 256>>>(atom, a_starts, a_sizes);
    cvt_w_kernel<<<(4 * H * H / 4) / 256, 256>>>(Wq, Wk, Wv, Wo);

    // fused QKV: N = 2304
    dim3 qkvgrid(2304 / BN, NROWS / BM);    // (18, 256)
    gemm_f16_kernel<true><<<qkvgrid, 256, GEMM_SMEM>>>(
        pXh, pWh, bq, bk, bv, nullptr, pP, a_sizes);

    attn_tc_kernel<<<dim3(NH, MOLS), ATT_THREADS, ATT_SMEM>>>(a_sizes);

    dim3 ogrid(H / BN, NROWS / BM);         // (6, 256)
    gemm_f16_kernel<false><<<ogrid, 256, GEMM_SMEM>>>(
        pCh, pWh + 3 * WSZ, bo, nullptr, nullptr, pCf, nullptr, a_sizes);

    ln_kernel<<<NROWS, 256>>>(atom, gamma, beta, a_starts, a_sizes, out);
}

// round 16
// speedup vs baseline: 1.0514x; 1.0514x over previous
#include <cuda_runtime.h>
#include <cuda_bf16.h>
#include <cuda_fp16.h>
#include <cstdint>

#define MOLS 128
#define L 256
#define H 768
#define NH 12
#define HD 64
#define NROWS (MOLS * L)
#define NRH ((size_t)NROWS * H)
#define SCALE2 0.1803368801111204f   /* HD^-0.5 * log2(e) */

// ---- GEMM tiling (pure fp16 single-term, BK=64, double buffer) ----
#define BM 128
#define BN 128
#define BK 64
#define KSTG (H / BK)        // 12
#define ROWB 144             // 64 fp16 = 128B data + 16B pad (conflict-free)
#define TILE_A (BM * ROWB)   // 18432
#define STAGE_BYTES (2 * TILE_A)           // A, B = 36864
#define GEMM_SMEM (2 * STAGE_BYTES)        // 73728  (x2 CTAs/SM = 147456)

// ---- attention smem layout (bytes), single fp16 K and V^T ----
#define ATT_K 0                            // 256 rows * 144
#define ATT_V 36864                        // 64 rows * 528
#define ATT_SMEM 70656
#define ATT_THREADS 512

// ---------------- scratch (device globals) ---------------------------------
__device__ __half g_Xh[NRH];                 // masked input, fp16
__device__ __half g_Ch[NRH];                 // attention ctx, fp16
__device__ __half g_Wh[4][(size_t)H * H];    // weights fp16 (Wq pre-scaled)
__device__ __half g_PRJ[3 * NRH];            // Q | K | V  (fp16)
__device__ float g_Cf[NRH];                  // O-projection output (fp32)

// ---------------- helpers ---------------------------------------------------
__device__ __forceinline__ uint32_t smem_u32(const void* p) {
    uint32_t a;
    asm("{ .reg .u64 t; cvta.to.shared.u64 t, %1; cvt.u32.u64 %0, t; }"
        : "=r"(a) : "l"(p));
    return a;
}
__device__ __forceinline__ float ex2(float x) {
    float y;
    asm("ex2.approx.ftz.f32 %0, %1;" : "=f"(y) : "f"(x));
    return y;
}
__device__ __forceinline__ void cp16(uint32_t s, const void* g) {
    asm volatile("cp.async.cg.shared.global [%0], [%1], 16;" :: "r"(s), "l"(g));
}
#define CP_COMMIT() asm volatile("cp.async.commit_group;" ::: "memory")
#define CP_WAIT0()  asm volatile("cp.async.wait_group 0;" ::: "memory")
#define LDM4(r0, r1, r2, r3, addr) \
    asm volatile("ldmatrix.sync.aligned.m8n8.x4.shared.b16 {%0,%1,%2,%3}, [%4];" \
                 : "=r"(r0), "=r"(r1), "=r"(r2), "=r"(r3) : "r"(addr))
__device__ __forceinline__ void mma_f16(float d[4], const uint32_t a[4],
                                        uint32_t b0, uint32_t b1) {
    asm volatile(
        "mma.sync.aligned.m16n8k16.row.col.f32.f16.f16.f32 "
        "{%0,%1,%2,%3}, {%4,%5,%6,%7}, {%8,%9}, {%0,%1,%2,%3};\n"
        : "+f"(d[0]), "+f"(d[1]), "+f"(d[2]), "+f"(d[3])
        : "r"(a[0]), "r"(a[1]), "r"(a[2]), "r"(a[3]), "r"(b0), "r"(b1));
}

// ---------------- masked gather -> fp16 --------------------------------------
__global__ void build_x_kernel(const float* __restrict__ atom,
                               const int* __restrict__ a_starts,
                               const int* __restrict__ a_sizes) {
    int i = blockIdx.x * blockDim.x + threadIdx.x;     // float4 index
    const int W4 = H / 4;
    int row = i / W4;
    int c4  = (i - row * W4) * 4;
    int m = row / L;
    int l = row - m * L;
    float4 val = make_float4(0.f, 0.f, 0.f, 0.f);
    if (l < a_sizes[m]) {
        int src = a_starts[m] + l;
        val = *(const float4*)&atom[(size_t)src * H + c4];
    }
    __half2 h0 = __float22half2_rn(make_float2(val.x, val.y));
    __half2 h1 = __float22half2_rn(make_float2(val.z, val.w));
    uint2 o;
    o.x = *(uint32_t*)&h0;
    o.y = *(uint32_t*)&h1;
    *(uint2*)&g_Xh[(size_t)row * H + c4] = o;
}

// ---------------- all 4 weights fp32 -> fp16 (Wq pre-scaled) ----------------
__global__ void cvt_w_kernel(const float* __restrict__ W0, const float* __restrict__ W1,
                             const float* __restrict__ W2, const float* __restrict__ W3) {
    int i = blockIdx.x * blockDim.x + threadIdx.x;     // float4 idx over 4*H*H
    const int PW = H * H / 4;
    int slab = i / PW;
    int j = i - slab * PW;
    const float* W = (slab == 0) ? W0 : (slab == 1) ? W1 : (slab == 2) ? W2 : W3;
    float sc = (slab == 0) ? SCALE2 : 1.f;
    float4 v = ((const float4*)W)[j];
    __half2 h0 = __float22half2_rn(make_float2(v.x * sc, v.y * sc));
    __half2 h1 = __float22half2_rn(make_float2(v.z * sc, v.w * sc));
    uint2 o;
    o.x = *(uint32_t*)&h0;
    o.y = *(uint32_t*)&h1;
    ((uint2*)&g_Wh[0][0])[i] = o;
}

// ---------------- fp16 GEMM: C[n,o] = A·Bᵗ + bias ---------------------------
// BK=64, distance-1 double buffer: wait(ks) -> sync -> issue(ks+1) -> compute(ks).
// Row-validity skip. (Round-14 validated configuration.)
template <bool SPLIT>
__global__ __launch_bounds__(256, 2) void gemm_f16_kernel(
    const __half* __restrict__ Ag, const __half* __restrict__ Bg,
    const float* __restrict__ b0, const float* __restrict__ b1,
    const float* __restrict__ b2, float* __restrict__ Cf,
    __half* __restrict__ Dh, const int* __restrict__ asz) {
    extern __shared__ char sm[];
    const uint32_t smb = smem_u32(sm);
    const int tid = threadIdx.x;
    const int lane = tid & 31;
    const int wid = tid >> 5;
    const int wm = wid >> 2;            // 0..1
    const int wn = wid & 3;             // 0..3
    const int bm = blockIdx.y * BM;
    const int bn = blockIdx.x * BN;

    // valid rows in this tile: molecule = blockIdx.y>>1, tile offset 0 or 128
    const int vt = asz[blockIdx.y >> 1] - ((blockIdx.y & 1) << 7);
    const int nmt = max(0, min(4, (vt - wm * 64 + 15) >> 4));   // valid subtiles

    float acc[4][4][4];
#pragma unroll
    for (int i = 0; i < 4; i++)
#pragma unroll
        for (int j = 0; j < 4; j++)
#pragma unroll
            for (int t = 0; t < 4; t++) acc[i][j][t] = 0.f;

    auto load_stage = [&](int buf, int k0) {
        uint32_t sb = smb + buf * STAGE_BYTES;
#pragma unroll
        for (int i = 0; i < 4; i++) {
            int c = tid + i * 256;               // 1024 chunks per tile
            int row = c >> 3, kc = c & 7;
            uint32_t so = row * ROWB + kc * 16;
            size_t go = (size_t)row * H + k0 + kc * 8;
            cp16(sb + so, Ag + (size_t)bm * H + go);
            cp16(sb + TILE_A + so, Bg + (size_t)bn * H + go);
        }
    };

    load_stage(0, 0);
    CP_COMMIT();

    const int trow = lane & 15;
    const int tkb = (lane >> 4) * 16;

#pragma unroll 1
    for (int ks = 0; ks < KSTG; ks++) {
        CP_WAIT0();                       // stage ks landed (ks+1 not yet issued)
        __syncthreads();                  // all warps done reading buffer (ks+1)&1
        if (ks + 1 < KSTG) {
            load_stage((ks + 1) & 1, (ks + 1) * BK);
            CP_COMMIT();
        }

        const uint32_t sA = smb + (ks & 1) * STAGE_BYTES;
        const uint32_t sB = sA + TILE_A;
        if (nmt > 0) {
#pragma unroll
            for (int kh = 0; kh < 4; kh++) {
                const uint32_t koff = kh * 32 + tkb;
                uint32_t av[4][4], bv[2][4];
#pragma unroll
                for (int mt = 0; mt < 4; mt++) {
                    if (mt < nmt) {
                        uint32_t a = sA + (wm * 64 + mt * 16 + trow) * ROWB + koff;
                        LDM4(av[mt][0], av[mt][1], av[mt][2], av[mt][3], a);
                    }
                }
#pragma unroll
                for (int g = 0; g < 2; g++) {
                    uint32_t b = sB + (wn * 32 + g * 16 + trow) * ROWB + koff;
                    LDM4(bv[g][0], bv[g][1], bv[g][2], bv[g][3], b);
                }
#pragma unroll
                for (int mt = 0; mt < 4; mt++) {
                    if (mt < nmt) {
#pragma unroll
                        for (int nt = 0; nt < 4; nt++) {
                            const int g = nt >> 1, s = nt & 1;
                            mma_f16(acc[mt][nt], av[mt], bv[g][s], bv[g][s + 2]);
                        }
                    }
                }
            }
        }
    }

    if (SPLIT) {
        const int sect = blockIdx.x / 6;                 // 0=Q 1=K 2=V
        const int coff = bn - sect * 768;
        const float* bias = (sect == 0) ? b0 : (sect == 1) ? b1 : b2;
        const float bscale = (sect == 0) ? SCALE2 : 1.f;
        __half* dh = Dh + (size_t)sect * NRH;
#pragma unroll
        for (int mt = 0; mt < 4; mt++) {
            if (mt >= nmt) continue;
            int row = bm + wm * 64 + mt * 16 + (lane >> 2);
#pragma unroll
            for (int nt = 0; nt < 4; nt++) {
                int cl = coff + wn * 32 + nt * 8 + (lane & 3) * 2;
                float bb0 = bias[cl] * bscale, bb1 = bias[cl + 1] * bscale;
                size_t o = (size_t)row * H + cl;
                __half2 v0 = __float22half2_rn(
                    make_float2(acc[mt][nt][0] + bb0, acc[mt][nt][1] + bb1));
                __half2 v1 = __float22half2_rn(
                    make_float2(acc[mt][nt][2] + bb0, acc[mt][nt][3] + bb1));
                *(uint32_t*)&dh[o] = *(uint32_t*)&v0;
                *(uint32_t*)&dh[o + 8 * H] = *(uint32_t*)&v1;
            }
        }
    } else {
#pragma unroll
        for (int mt = 0; mt < 4; mt++) {
            if (mt >= nmt) continue;
            int row = bm + wm * 64 + mt * 16 + (lane >> 2);
#pragma unroll
            for (int nt = 0; nt < 4; nt++) {
                int col = bn + wn * 32 + nt * 8 + (lane & 3) * 2;
                float2 bb = *(const float2*)&b0[col];
                float* p = Cf + (size_t)row * H + col;
                *(float2*)p = make_float2(acc[mt][nt][0] + bb.x, acc[mt][nt][1] + bb.y);
                *(float2*)(p + 8 * H) =
                    make_float2(acc[mt][nt][2] + bb.x, acc[mt][nt][3] + bb.y);
            }
        }
    }
}

// ---------------- tensor-core flash attention (single fp16) -----------------
// One 512-thread CTA per (head, molecule): K/V staged ONCE; warp w handles
// q rows [w*16, w*16+16); warps entirely in padding exit after staging.
__global__ __launch_bounds__(ATT_THREADS, 1) void attn_tc_kernel(
    const int* __restrict__ a_sizes) {
    extern __shared__ char sm[];
    const uint32_t smb = smem_u32(sm);
    const int h = blockIdx.x, m = blockIdx.y;
    const int tid = threadIdx.x;
    const int lane = tid & 31;
    const int wid = tid >> 5;
    const int size = a_sizes[m];

    const __half* Qh = g_PRJ;
    const __half* Kh = g_PRJ + NRH;
    const __half* Vh = g_PRJ + 2 * NRH;

    // ---- stage K (row-major, pitch 144B): pure 16B copies ----
#pragma unroll
    for (int it = 0; it < 4; it++) {
        int i = tid + it * ATT_THREADS;
        int row = i >> 3, ch = (i & 7) * 8;
        size_t src = (size_t)(m * L + row) * H + h * HD + ch;
        *(uint4*)(sm + ATT_K + row * 144 + ch * 2) = *(const uint4*)&Kh[src];
    }
    // ---- stage V^T (pitch 528B): transpose via 2B reads ----
#pragma unroll
    for (int it = 0; it < 16; it++) {
        int p = tid + it * ATT_THREADS;
        int d = p & 63, j = (p >> 6) * 2;
        size_t s0 = (size_t)(m * L + j) * H + h * HD + d;
        uint32_t v0 = *(const unsigned short*)&Vh[s0];
        uint32_t v1 = *(const unsigned short*)&Vh[s0 + H];
        *(uint32_t*)(sm + ATT_V + d * 528 + j * 2) = v0 | (v1 << 16);
    }
    __syncthreads();

    // warps fully in the padding region do no attention work
    if (wid * 16 >= size) return;

    const int tq2 = (lane & 3) * 2;
    const int l15 = lane & 15;
    const int lhk = (lane >> 4) * 16;
    const int row0 = wid * 16 + (lane >> 2);

    // Q fragments straight from gmem (already scaled, fp16)
    uint32_t qv[4][4];
    {
        const size_t qb = (size_t)(m * L + row0) * H + h * HD;
#pragma unroll
        for (int ks = 0; ks < 4; ks++) {
            int k = ks * 16 + tq2;
            qv[ks][0] = *(const uint32_t*)&Qh[qb + k];
            qv[ks][1] = *(const uint32_t*)&Qh[qb + 8 * H + k];
            qv[ks][2] = *(const uint32_t*)&Qh[qb + k + 8];
            qv[ks][3] = *(const uint32_t*)&Qh[qb + 8 * H + k + 8];
        }
    }

    float O[8][4];
#pragma unroll
    for (int i = 0; i < 8; i++)
#pragma unroll
        for (int j = 0; j < 4; j++) O[i][j] = 0.f;
    float m0 = -1e30f, m1 = -1e30f, l0 = 0.f, l1 = 0.f;

    const int nch = min(4, (size + 63) >> 6);
#pragma unroll 1
    for (int c = 0; c < nch; c++) {
        const int j0 = c * 64;
        float S[8][4];
#pragma unroll
        for (int i = 0; i < 8; i++)
#pragma unroll
            for (int j = 0; j < 4; j++) S[i][j] = 0.f;

        // ---- QK: S = Q'·K^T (log2 domain) ----
#pragma unroll
        for (int np = 0; np < 4; np++) {
            uint32_t kra = smb + ATT_K + (j0 + np * 16 + l15) * 144 + lhk;
#pragma unroll
            for (int ks = 0; ks < 4; ks++) {
                uint32_t k0, k1, k2, k3;
                LDM4(k0, k1, k2, k3, kra + ks * 32);
                mma_f16(S[2 * np], qv[ks], k0, k2);
                mma_f16(S[2 * np + 1], qv[ks], k1, k3);
            }
        }

        // ---- mask boundary chunk ----
        if (j0 + 64 > size) {
#pragma unroll
            for (int nt = 0; nt < 8; nt++) {
                int col = j0 + nt * 8 + tq2;
                if (col >= size)     { S[nt][0] = -1e30f; S[nt][2] = -1e30f; }
                if (col + 1 >= size) { S[nt][1] = -1e30f; S[nt][3] = -1e30f; }
            }
        }

        // ---- online softmax on fragments ----
        float mx0 = -1e30f, mx1 = -1e30f;
#pragma unroll
        for (int nt = 0; nt < 8; nt++) {
            mx0 = fmaxf(mx0, fmaxf(S[nt][0], S[nt][1]));
            mx1 = fmaxf(mx1, fmaxf(S[nt][2], S[nt][3]));
        }
        mx0 = fmaxf(mx0, __shfl_xor_sync(0xffffffffu, mx0, 1));
        mx0 = fmaxf(mx0, __shfl_xor_sync(0xffffffffu, mx0, 2));
        mx1 = fmaxf(mx1, __shfl_xor_sync(0xffffffffu, mx1, 1));
        mx1 = fmaxf(mx1, __shfl_xor_sync(0xffffffffu, mx1, 2));
        float nm0 = fmaxf(m0, mx0), nm1 = fmaxf(m1, mx1);
        float f0 = ex2(m0 - nm0), f1 = ex2(m1 - nm1);
        float rs0 = 0.f, rs1 = 0.f;
#pragma unroll
        for (int nt = 0; nt < 8; nt++) {
            S[nt][0] = ex2(S[nt][0] - nm0); rs0 += S[nt][0];
            S[nt][1] = ex2(S[nt][1] - nm0); rs0 += S[nt][1];
            S[nt][2] = ex2(S[nt][2] - nm1); rs1 += S[nt][2];
            S[nt][3] = ex2(S[nt][3] - nm1); rs1 += S[nt][3];
        }
        rs0 += __shfl_xor_sync(0xffffffffu, rs0, 1);
        rs0 += __shfl_xor_sync(0xffffffffu, rs0, 2);
        rs1 += __shfl_xor_sync(0xffffffffu, rs1, 1);
        rs1 += __shfl_xor_sync(0xffffffffu, rs1, 2);
        l0 = l0 * f0 + rs0;
        l1 = l1 * f1 + rs1;
        m0 = nm0; m1 = nm1;
#pragma unroll
        for (int dt = 0; dt < 8; dt++) {
            O[dt][0] *= f0; O[dt][1] *= f0;
            O[dt][2] *= f1; O[dt][3] *= f1;
        }

        // ---- P fragments (single fp16) ----
        uint32_t pv[4][4];
#pragma unroll
        for (int ks = 0; ks < 4; ks++) {
            __half2 p0 = __float22half2_rn(make_float2(S[2 * ks][0], S[2 * ks][1]));
            __half2 p1 = __float22half2_rn(make_float2(S[2 * ks][2], S[2 * ks][3]));
            __half2 p2 = __float22half2_rn(make_float2(S[2 * ks + 1][0], S[2 * ks + 1][1]));
            __half2 p3 = __float22half2_rn(make_float2(S[2 * ks + 1][2], S[2 * ks + 1][3]));
            pv[ks][0] = *(uint32_t*)&p0;
            pv[ks][1] = *(uint32_t*)&p1;
            pv[ks][2] = *(uint32_t*)&p2;
            pv[ks][3] = *(uint32_t*)&p3;
        }

        // ---- PV: O += P·V ----
#pragma unroll
        for (int dp = 0; dp < 4; dp++) {
            uint32_t vra = smb + ATT_V + (dp * 16 + l15) * 528 + j0 * 2 + lhk;
#pragma unroll
            for (int ks = 0; ks < 4; ks++) {
                uint32_t v0, v1, v2, v3;
                LDM4(v0, v1, v2, v3, vra + ks * 32);
                mma_f16(O[2 * dp], pv[ks], v0, v2);
                mma_f16(O[2 * dp + 1], pv[ks], v1, v3);
            }
        }
    }

    // ---- normalize + write ctx fp16 ----
    const float i0 = 1.f / l0, i1 = 1.f / l1;
    const size_t ob = (size_t)(m * L + row0) * H + h * HD + tq2;
#pragma unroll
    for (int dt = 0; dt < 8; dt++) {
        __half2 c0 = __float22half2_rn(make_float2(O[dt][0] * i0, O[dt][1] * i0));
        __half2 c1 = __float22half2_rn(make_float2(O[dt][2] * i1, O[dt][3] * i1));
        *(uint32_t*)&g_Ch[ob + dt * 8] = *(uint32_t*)&c0;
        *(uint32_t*)&g_Ch[ob + 8 * H + dt * 8] = *(uint32_t*)&c1;
    }
}

// -------- residual + LayerNorm + mask + scatter (covers ALL rows) ----------
__global__ __launch_bounds__(256) void ln_kernel(
    const float* __restrict__ atom,
    const float* __restrict__ gamma, const float* __restrict__ beta,
    const int* __restrict__ a_starts, const int* __restrict__ a_sizes,
    float* __restrict__ out) {
    const int row = blockIdx.x;
    const int m = row / L;
    const int l = row - m * L;
    const int tid = threadIdx.x;

    const bool valid = l < a_sizes[m];
    const int dst = a_starts[m] + l;

    if (!valid) {   // uniform across block: padding rows just write zeros
#pragma unroll
        for (int i = 0; i < 3; i++)
            out[(size_t)dst * H + tid + i * 256] = 0.f;
        return;
    }

    __shared__ float redbuf[8];
    __shared__ float stat[2];

    float y[3];
    float s = 0.f;
#pragma unroll
    for (int i = 0; i < 3; i++) {
        int col = tid + i * 256;
        float v = g_Cf[(size_t)row * H + col] + atom[(size_t)dst * H + col];
        y[i] = v;
        s += v;
    }
#pragma unroll
    for (int o = 16; o > 0; o >>= 1) s += __shfl_xor_sync(0xffffffffu, s, o);
    if ((tid & 31) == 0) redbuf[tid >> 5] = s;
    __syncthreads();
    if (tid == 0) {
        float t = 0.f;
#pragma unroll
        for (int i = 0; i < 8; i++) t += redbuf[i];
        stat[0] = t;
    }
    __syncthreads();
    const float mu = stat[0] * (1.f / 768.f);

    float vs = 0.f;
#pragma unroll
    for (int i = 0; i < 3; i++) {
        float d = y[i] - mu;
        vs += d * d;
    }
#pragma unroll
    for (int o = 16; o > 0; o >>= 1) vs += __shfl_xor_sync(0xffffffffu, vs, o);
    if ((tid & 31) == 0) redbuf[tid >> 5] = vs;
    __syncthreads();
    if (tid == 0) {
        float t = 0.f;
#pragma unroll
        for (int i = 0; i < 8; i++) t += redbuf[i];
        stat[1] = t;
    }
    __syncthreads();
    const float rstd = rsqrtf(stat[1] * (1.f / 768.f) + 1e-5f);

#pragma unroll
    for (int i = 0; i < 3; i++) {
        int col = tid + i * 256;
        out[(size_t)dst * H + col] = (y[i] - mu) * rstd * gamma[col] + beta[col];
    }
}

// ---------------------------------------------------------------------------
extern "C" void kernel_launch(void* const* d_in, const int* in_sizes, int n_in,
                              void* d_out, int out_size) {
    const float* atom     = (const float*)d_in[0];
    const float* Wq       = (const float*)d_in[1];
    const float* bq       = (const float*)d_in[2];
    const float* Wk       = (const float*)d_in[3];
    const float* bk       = (const float*)d_in[4];
    const float* Wv       = (const float*)d_in[5];
    const float* bv       = (const float*)d_in[6];
    const float* Wo       = (const float*)d_in[7];
    const float* bo       = (const float*)d_in[8];
    const float* gamma    = (const float*)d_in[9];
    const float* beta     = (const float*)d_in[10];
    const int*   a_starts = (const int*)d_in[11];
    const int*   a_sizes  = (const int*)d_in[12];
    float* out = (float*)d_out;

    __half *pXh, *pCh, *pWh, *pP;
    float* pCf;
    cudaGetSymbolAddress((void**)&pXh, g_Xh);
    cudaGetSymbolAddress((void**)&pCh, g_Ch);
    cudaGetSymbolAddress((void**)&pWh, g_Wh);
    cudaGetSymbolAddress((void**)&pP, g_PRJ);
    cudaGetSymbolAddress((void**)&pCf, g_Cf);
    const size_t WSZ = (size_t)H * H;

    cudaFuncSetAttribute(attn_tc_kernel, cudaFuncAttributeMaxDynamicSharedMemorySize,
                         ATT_SMEM);
    cudaFuncSetAttribute(gemm_f16_kernel<true>,
                         cudaFuncAttributeMaxDynamicSharedMemorySize, GEMM_SMEM);
    cudaFuncSetAttribute(gemm_f16_kernel<false>,
                         cudaFuncAttributeMaxDynamicSharedMemorySize, GEMM_SMEM);

    build_x_kernel<<<(NROWS * H / 4) / 256, 256>>>(atom, a_starts, a_sizes);
    cvt_w_kernel<<<(4 * H * H / 4) / 256, 256>>>(Wq, Wk, Wv, Wo);

    // fused QKV: N = 2304
    dim3 qkvgrid(2304 / BN, NROWS / BM);    // (18, 256)
    gemm_f16_kernel<true><<<qkvgrid, 256, GEMM_SMEM>>>(
        pXh, pWh, bq, bk, bv, nullptr, pP, a_sizes);

    attn_tc_kernel<<<dim3(NH, MOLS), ATT_THREADS, ATT_SMEM>>>(a_sizes);

    dim3 ogrid(H / BN, NROWS / BM);         // (6, 256)
    gemm_f16_kernel<false><<<ogrid, 256, GEMM_SMEM>>>(
        pCh, pWh + 3 * WSZ, bo, nullptr, nullptr, pCf, nullptr, a_sizes);

    ln_kernel<<<NROWS, 256>>>(atom, gamma, beta, a_starts, a_sizes, out);
}

// round 17
// speedup vs baseline: 1.0546x; 1.0031x over previous
#include <cuda_runtime.h>
#include <cuda_bf16.h>
#include <cuda_fp16.h>
#include <cstdint>

#define MOLS 128
#define L 256
#define H 768
#define NH 12
#define HD 64
#define NROWS (MOLS * L)
#define NRH ((size_t)NROWS * H)
#define SCALE2 0.1803368801111204f   /* HD^-0.5 * log2(e) */

// ---- GEMM tiling (pure fp16 single-term, BK=64, double buffer) ----
#define BM 128
#define BN 128
#define BK 64
#define KSTG (H / BK)        // 12
#define ROWB 144             // 64 fp16 = 128B data + 16B pad (conflict-free)
#define TILE_A (BM * ROWB)   // 18432
#define STAGE_BYTES (2 * TILE_A)           // A, B = 36864
#define GEMM_SMEM (2 * STAGE_BYTES)        // 73728  (x2 CTAs/SM = 147456)

// ---- attention smem layout (bytes), single fp16 K and V^T ----
#define ATT_K 0                            // 256 rows * 144
#define ATT_V 36864                        // 64 rows * 528
#define ATT_SMEM 70656
#define ATT_THREADS 512

// ---------------- scratch (device globals) ---------------------------------
__device__ __half g_Xh[NRH];                 // masked input, fp16
__device__ __half g_Ch[NRH];                 // attention ctx, fp16
__device__ __half g_Wh[4][(size_t)H * H];    // weights fp16 (Wq pre-scaled)
__device__ __half g_PRJ[3 * NRH];            // Q | K | V  (fp16)
__device__ float g_Cf[NRH];                  // O-projection output (fp32)

// ---------------- helpers ---------------------------------------------------
__device__ __forceinline__ uint32_t smem_u32(const void* p) {
    uint32_t a;
    asm("{ .reg .u64 t; cvta.to.shared.u64 t, %1; cvt.u32.u64 %0, t; }"
        : "=r"(a) : "l"(p));
    return a;
}
__device__ __forceinline__ float ex2(float x) {
    float y;
    asm("ex2.approx.ftz.f32 %0, %1;" : "=f"(y) : "f"(x));
    return y;
}
__device__ __forceinline__ void cp16(uint32_t s, const void* g) {
    asm volatile("cp.async.cg.shared.global [%0], [%1], 16;" :: "r"(s), "l"(g));
}
#define CP_COMMIT() asm volatile("cp.async.commit_group;" ::: "memory")
#define CP_WAIT0()  asm volatile("cp.async.wait_group 0;" ::: "memory")
#define LDM4(r0, r1, r2, r3, addr) \
    asm volatile("ldmatrix.sync.aligned.m8n8.x4.shared.b16 {%0,%1,%2,%3}, [%4];" \
                 : "=r"(r0), "=r"(r1), "=r"(r2), "=r"(r3) : "r"(addr))
__device__ __forceinline__ void mma_f16(float d[4], const uint32_t a[4],
                                        uint32_t b0, uint32_t b1) {
    asm volatile(
        "mma.sync.aligned.m16n8k16.row.col.f32.f16.f16.f32 "
        "{%0,%1,%2,%3}, {%4,%5,%6,%7}, {%8,%9}, {%0,%1,%2,%3};\n"
        : "+f"(d[0]), "+f"(d[1]), "+f"(d[2]), "+f"(d[3])
        : "r"(a[0]), "r"(a[1]), "r"(a[2]), "r"(a[3]), "r"(b0), "r"(b1));
}

// ---------------- masked gather -> fp16 --------------------------------------
__global__ void build_x_kernel(const float* __restrict__ atom,
                               const int* __restrict__ a_starts,
                               const int* __restrict__ a_sizes) {
    int i = blockIdx.x * blockDim.x + threadIdx.x;     // float4 index
    const int W4 = H / 4;
    int row = i / W4;
    int c4  = (i - row * W4) * 4;
    int m = row / L;
    int l = row - m * L;
    float4 val = make_float4(0.f, 0.f, 0.f, 0.f);
    if (l < a_sizes[m]) {
        int src = a_starts[m] + l;
        val = *(const float4*)&atom[(size_t)src * H + c4];
    }
    __half2 h0 = __float22half2_rn(make_float2(val.x, val.y));
    __half2 h1 = __float22half2_rn(make_float2(val.z, val.w));
    uint2 o;
    o.x = *(uint32_t*)&h0;
    o.y = *(uint32_t*)&h1;
    *(uint2*)&g_Xh[(size_t)row * H + c4] = o;
}

// ---------------- all 4 weights fp32 -> fp16 (Wq pre-scaled) ----------------
__global__ void cvt_w_kernel(const float* __restrict__ W0, const float* __restrict__ W1,
                             const float* __restrict__ W2, const float* __restrict__ W3) {
    int i = blockIdx.x * blockDim.x + threadIdx.x;     // float4 idx over 4*H*H
    const int PW = H * H / 4;
    int slab = i / PW;
    int j = i - slab * PW;
    const float* W = (slab == 0) ? W0 : (slab == 1) ? W1 : (slab == 2) ? W2 : W3;
    float sc = (slab == 0) ? SCALE2 : 1.f;
    float4 v = ((const float4*)W)[j];
    __half2 h0 = __float22half2_rn(make_float2(v.x * sc, v.y * sc));
    __half2 h1 = __float22half2_rn(make_float2(v.z * sc, v.w * sc));
    uint2 o;
    o.x = *(uint32_t*)&h0;
    o.y = *(uint32_t*)&h1;
    ((uint2*)&g_Wh[0][0])[i] = o;
}

// ---------------- fp16 GEMM: C[n,o] = A·Bᵗ + bias ---------------------------
// BK=64, distance-1 double buffer. Clean (unpredicated) fast path for the
// common all-valid case nmt==4; predicated path only for boundary tiles.
template <bool SPLIT>
__global__ __launch_bounds__(256, 2) void gemm_f16_kernel(
    const __half* __restrict__ Ag, const __half* __restrict__ Bg,
    const float* __restrict__ b0, const float* __restrict__ b1,
    const float* __restrict__ b2, float* __restrict__ Cf,
    __half* __restrict__ Dh, const int* __restrict__ asz) {
    extern __shared__ char sm[];
    const uint32_t smb = smem_u32(sm);
    const int tid = threadIdx.x;
    const int lane = tid & 31;
    const int wid = tid >> 5;
    const int wm = wid >> 2;            // 0..1
    const int wn = wid & 3;             // 0..3
    const int bm = blockIdx.y * BM;
    const int bn = blockIdx.x * BN;

    const int vt = asz[blockIdx.y >> 1] - ((blockIdx.y & 1) << 7);
    const int nmt = max(0, min(4, (vt - wm * 64 + 15) >> 4));   // valid subtiles

    float acc[4][4][4];
#pragma unroll
    for (int i = 0; i < 4; i++)
#pragma unroll
        for (int j = 0; j < 4; j++)
#pragma unroll
            for (int t = 0; t < 4; t++) acc[i][j][t] = 0.f;

    auto load_stage = [&](int buf, int k0) {
        uint32_t sb = smb + buf * STAGE_BYTES;
#pragma unroll
        for (int i = 0; i < 4; i++) {
            int c = tid + i * 256;               // 1024 chunks per tile
            int row = c >> 3, kc = c & 7;
            uint32_t so = row * ROWB + kc * 16;
            size_t go = (size_t)row * H + k0 + kc * 8;
            cp16(sb + so, Ag + (size_t)bm * H + go);
            cp16(sb + TILE_A + so, Bg + (size_t)bn * H + go);
        }
    };

    load_stage(0, 0);
    CP_COMMIT();

    const int trow = lane & 15;
    const int tkb = (lane >> 4) * 16;

#pragma unroll 1
    for (int ks = 0; ks < KSTG; ks++) {
        CP_WAIT0();
        __syncthreads();
        if (ks + 1 < KSTG) {
            load_stage((ks + 1) & 1, (ks + 1) * BK);
            CP_COMMIT();
        }

        const uint32_t sA = smb + (ks & 1) * STAGE_BYTES;
        const uint32_t sB = sA + TILE_A;
        if (nmt == 4) {
            // ---- fast path: all subtiles valid, no predication ----
#pragma unroll
            for (int kh = 0; kh < 4; kh++) {
                const uint32_t koff = kh * 32 + tkb;
                uint32_t av[4][4], bv[2][4];
#pragma unroll
                for (int mt = 0; mt < 4; mt++) {
                    uint32_t a = sA + (wm * 64 + mt * 16 + trow) * ROWB + koff;
                    LDM4(av[mt][0], av[mt][1], av[mt][2], av[mt][3], a);
                }
#pragma unroll
                for (int g = 0; g < 2; g++) {
                    uint32_t b = sB + (wn * 32 + g * 16 + trow) * ROWB + koff;
                    LDM4(bv[g][0], bv[g][1], bv[g][2], bv[g][3], b);
                }
#pragma unroll
                for (int mt = 0; mt < 4; mt++)
#pragma unroll
                    for (int nt = 0; nt < 4; nt++) {
                        const int g = nt >> 1, s = nt & 1;
                        mma_f16(acc[mt][nt], av[mt], bv[g][s], bv[g][s + 2]);
                    }
            }
        } else if (nmt > 0) {
#pragma unroll
            for (int kh = 0; kh < 4; kh++) {
                const uint32_t koff = kh * 32 + tkb;
                uint32_t av[4][4], bv[2][4];
#pragma unroll
                for (int mt = 0; mt < 4; mt++) {
                    if (mt < nmt) {
                        uint32_t a = sA + (wm * 64 + mt * 16 + trow) * ROWB + koff;
                        LDM4(av[mt][0], av[mt][1], av[mt][2], av[mt][3], a);
                    }
                }
#pragma unroll
                for (int g = 0; g < 2; g++) {
                    uint32_t b = sB + (wn * 32 + g * 16 + trow) * ROWB + koff;
                    LDM4(bv[g][0], bv[g][1], bv[g][2], bv[g][3], b);
                }
#pragma unroll
                for (int mt = 0; mt < 4; mt++) {
                    if (mt < nmt) {
#pragma unroll
                        for (int nt = 0; nt < 4; nt++) {
                            const int g = nt >> 1, s = nt & 1;
                            mma_f16(acc[mt][nt], av[mt], bv[g][s], bv[g][s + 2]);
                        }
                    }
                }
            }
        }
    }

    if (SPLIT) {
        const int sect = blockIdx.x / 6;                 // 0=Q 1=K 2=V
        const int coff = bn - sect * 768;
        const float* bias = (sect == 0) ? b0 : (sect == 1) ? b1 : b2;
        const float bscale = (sect == 0) ? SCALE2 : 1.f;
        __half* dh = Dh + (size_t)sect * NRH;
#pragma unroll
        for (int mt = 0; mt < 4; mt++) {
            if (mt >= nmt) continue;
            int row = bm + wm * 64 + mt * 16 + (lane >> 2);
#pragma unroll
            for (int nt = 0; nt < 4; nt++) {
                int cl = coff + wn * 32 + nt * 8 + (lane & 3) * 2;
                float bb0 = bias[cl] * bscale, bb1 = bias[cl + 1] * bscale;
                size_t o = (size_t)row * H + cl;
                __half2 v0 = __float22half2_rn(
                    make_float2(acc[mt][nt][0] + bb0, acc[mt][nt][1] + bb1));
                __half2 v1 = __float22half2_rn(
                    make_float2(acc[mt][nt][2] + bb0, acc[mt][nt][3] + bb1));
                *(uint32_t*)&dh[o] = *(uint32_t*)&v0;
                *(uint32_t*)&dh[o + 8 * H] = *(uint32_t*)&v1;
            }
        }
    } else {
#pragma unroll
        for (int mt = 0; mt < 4; mt++) {
            if (mt >= nmt) continue;
            int row = bm + wm * 64 + mt * 16 + (lane >> 2);
#pragma unroll
            for (int nt = 0; nt < 4; nt++) {
                int col = bn + wn * 32 + nt * 8 + (lane & 3) * 2;
                float2 bb = *(const float2*)&b0[col];
                float* p = Cf + (size_t)row * H + col;
                *(float2*)p = make_float2(acc[mt][nt][0] + bb.x, acc[mt][nt][1] + bb.y);
                *(float2*)(p + 8 * H) =
                    make_float2(acc[mt][nt][2] + bb.x, acc[mt][nt][3] + bb.y);
            }
        }
    }
}

// ---------------- tensor-core flash attention (single fp16) -----------------
// One 512-thread CTA per (head, molecule): K/V staged ONCE; warp w handles
// q rows [w*16, w*16+16); warps entirely in padding exit after staging.
__global__ __launch_bounds__(ATT_THREADS, 1) void attn_tc_kernel(
    const int* __restrict__ a_sizes) {
    extern __shared__ char sm[];
    const uint32_t smb = smem_u32(sm);
    const int h = blockIdx.x, m = blockIdx.y;
    const int tid = threadIdx.x;
    const int lane = tid & 31;
    const int wid = tid >> 5;
    const int size = a_sizes[m];

    const __half* Qh = g_PRJ;
    const __half* Kh = g_PRJ + NRH;
    const __half* Vh = g_PRJ + 2 * NRH;

#pragma unroll
    for (int it = 0; it < 4; it++) {
        int i = tid + it * ATT_THREADS;
        int row = i >> 3, ch = (i & 7) * 8;
        size_t src = (size_t)(m * L + row) * H + h * HD + ch;
        *(uint4*)(sm + ATT_K + row * 144 + ch * 2) = *(const uint4*)&Kh[src];
    }
#pragma unroll
    for (int it = 0; it < 16; it++) {
        int p = tid + it * ATT_THREADS;
        int d = p & 63, j = (p >> 6) * 2;
        size_t s0 = (size_t)(m * L + j) * H + h * HD + d;
        uint32_t v0 = *(const unsigned short*)&Vh[s0];
        uint32_t v1 = *(const unsigned short*)&Vh[s0 + H];
        *(uint32_t*)(sm + ATT_V + d * 528 + j * 2) = v0 | (v1 << 16);
    }
    __syncthreads();

    if (wid * 16 >= size) return;

    const int tq2 = (lane & 3) * 2;
    const int l15 = lane & 15;
    const int lhk = (lane >> 4) * 16;
    const int row0 = wid * 16 + (lane >> 2);

    uint32_t qv[4][4];
    {
        const size_t qb = (size_t)(m * L + row0) * H + h * HD;
#pragma unroll
        for (int ks = 0; ks < 4; ks++) {
            int k = ks * 16 + tq2;
            qv[ks][0] = *(const uint32_t*)&Qh[qb + k];
            qv[ks][1] = *(const uint32_t*)&Qh[qb + 8 * H + k];
            qv[ks][2] = *(const uint32_t*)&Qh[qb + k + 8];
            qv[ks][3] = *(const uint32_t*)&Qh[qb + 8 * H + k + 8];
        }
    }

    float O[8][4];
#pragma unroll
    for (int i = 0; i < 8; i++)
#pragma unroll
        for (int j = 0; j < 4; j++) O[i][j] = 0.f;
    float m0 = -1e30f, m1 = -1e30f, l0 = 0.f, l1 = 0.f;

    const int nch = min(4, (size + 63) >> 6);
#pragma unroll 1
    for (int c = 0; c < nch; c++) {
        const int j0 = c * 64;
        float S[8][4];
#pragma unroll
        for (int i = 0; i < 8; i++)
#pragma unroll
            for (int j = 0; j < 4; j++) S[i][j] = 0.f;

#pragma unroll
        for (int np = 0; np < 4; np++) {
            uint32_t kra = smb + ATT_K + (j0 + np * 16 + l15) * 144 + lhk;
#pragma unroll
            for (int ks = 0; ks < 4; ks++) {
                uint32_t k0, k1, k2, k3;
                LDM4(k0, k1, k2, k3, kra + ks * 32);
                mma_f16(S[2 * np], qv[ks], k0, k2);
                mma_f16(S[2 * np + 1], qv[ks], k1, k3);
            }
        }

        if (j0 + 64 > size) {
#pragma unroll
            for (int nt = 0; nt < 8; nt++) {
                int col = j0 + nt * 8 + tq2;
                if (col >= size)     { S[nt][0] = -1e30f; S[nt][2] = -1e30f; }
                if (col + 1 >= size) { S[nt][1] = -1e30f; S[nt][3] = -1e30f; }
            }
        }

        float mx0 = -1e30f, mx1 = -1e30f;
#pragma unroll
        for (int nt = 0; nt < 8; nt++) {
            mx0 = fmaxf(mx0, fmaxf(S[nt][0], S[nt][1]));
            mx1 = fmaxf(mx1, fmaxf(S[nt][2], S[nt][3]));
        }
        mx0 = fmaxf(mx0, __shfl_xor_sync(0xffffffffu, mx0, 1));
        mx0 = fmaxf(mx0, __shfl_xor_sync(0xffffffffu, mx0, 2));
        mx1 = fmaxf(mx1, __shfl_xor_sync(0xffffffffu, mx1, 1));
        mx1 = fmaxf(mx1, __shfl_xor_sync(0xffffffffu, mx1, 2));
        float nm0 = fmaxf(m0, mx0), nm1 = fmaxf(m1, mx1);
        float rs0 = 0.f, rs1 = 0.f;
#pragma unroll
        for (int nt = 0; nt < 8; nt++) {
            S[nt][0] = ex2(S[nt][0] - nm0); rs0 += S[nt][0];
            S[nt][1] = ex2(S[nt][1] - nm0); rs0 += S[nt][1];
            S[nt][2] = ex2(S[nt][2] - nm1); rs1 += S[nt][2];
            S[nt][3] = ex2(S[nt][3] - nm1); rs1 += S[nt][3];
        }
        rs0 += __shfl_xor_sync(0xffffffffu, rs0, 1);
        rs0 += __shfl_xor_sync(0xffffffffu, rs0, 2);
        rs1 += __shfl_xor_sync(0xffffffffu, rs1, 1);
        rs1 += __shfl_xor_sync(0xffffffffu, rs1, 2);
        if (c > 0) {
            // rescale previous state (exact: on c==0, f==0 and O==0, l==0)
            float f0 = ex2(m0 - nm0), f1 = ex2(m1 - nm1);
            l0 = l0 * f0 + rs0;
            l1 = l1 * f1 + rs1;
#pragma unroll
            for (int dt = 0; dt < 8; dt++) {
                O[dt][0] *= f0; O[dt][1] *= f0;
                O[dt][2] *= f1; O[dt][3] *= f1;
            }
        } else {
            l0 = rs0;
            l1 = rs1;
        }
        m0 = nm0; m1 = nm1;

        uint32_t pv[4][4];
#pragma unroll
        for (int ks = 0; ks < 4; ks++) {
            __half2 p0 = __float22half2_rn(make_float2(S[2 * ks][0], S[2 * ks][1]));
            __half2 p1 = __float22half2_rn(make_float2(S[2 * ks][2], S[2 * ks][3]));
            __half2 p2 = __float22half2_rn(make_float2(S[2 * ks + 1][0], S[2 * ks + 1][1]));
            __half2 p3 = __float22half2_rn(make_float2(S[2 * ks + 1][2], S[2 * ks + 1][3]));
            pv[ks][0] = *(uint32_t*)&p0;
            pv[ks][1] = *(uint32_t*)&p1;
            pv[ks][2] = *(uint32_t*)&p2;
            pv[ks][3] = *(uint32_t*)&p3;
        }

#pragma unroll
        for (int dp = 0; dp < 4; dp++) {
            uint32_t vra = smb + ATT_V + (dp * 16 + l15) * 528 + j0 * 2 + lhk;
#pragma unroll
            for (int ks = 0; ks < 4; ks++) {
                uint32_t v0, v1, v2, v3;
                LDM4(v0, v1, v2, v3, vra + ks * 32);
                mma_f16(O[2 * dp], pv[ks], v0, v2);
                mma_f16(O[2 * dp + 1], pv[ks], v1, v3);
            }
        }
    }

    const float i0 = 1.f / l0, i1 = 1.f / l1;
    const size_t ob = (size_t)(m * L + row0) * H + h * HD + tq2;
#pragma unroll
    for (int dt = 0; dt < 8; dt++) {
        __half2 c0 = __float22half2_rn(make_float2(O[dt][0] * i0, O[dt][1] * i0));
        __half2 c1 = __float22half2_rn(make_float2(O[dt][2] * i1, O[dt][3] * i1));
        *(uint32_t*)&g_Ch[ob + dt * 8] = *(uint32_t*)&c0;
        *(uint32_t*)&g_Ch[ob + 8 * H + dt * 8] = *(uint32_t*)&c1;
    }
}

// -------- residual + LayerNorm + mask + scatter (single-pass moments) ------
__global__ __launch_bounds__(256) void ln_kernel(
    const float* __restrict__ atom,
    const float* __restrict__ gamma, const float* __restrict__ beta,
    const int* __restrict__ a_starts, const int* __restrict__ a_sizes,
    float* __restrict__ out) {
    const int row = blockIdx.x;
    const int m = row / L;
    const int l = row - m * L;
    const int tid = threadIdx.x;

    const bool valid = l < a_sizes[m];
    const int dst = a_starts[m] + l;

    if (!valid) {   // uniform across block: padding rows just write zeros
#pragma unroll
        for (int i = 0; i < 3; i++)
            out[(size_t)dst * H + tid + i * 256] = 0.f;
        return;
    }

    __shared__ float redbuf[16];
    __shared__ float stat[2];

    float y[3];
    float s = 0.f, s2 = 0.f;
#pragma unroll
    for (int i = 0; i < 3; i++) {
        int col = tid + i * 256;
        float v = g_Cf[(size_t)row * H + col] + atom[(size_t)dst * H + col];
        y[i] = v;
        s += v;
        s2 = fmaf(v, v, s2);
    }
#pragma unroll
    for (int o = 16; o > 0; o >>= 1) {
        s  += __shfl_xor_sync(0xffffffffu, s,  o);
        s2 += __shfl_xor_sync(0xffffffffu, s2, o);
    }
    if ((tid & 31) == 0) {
        redbuf[tid >> 5] = s;
        redbuf[8 + (tid >> 5)] = s2;
    }
    __syncthreads();
    if (tid == 0) {
        float t = 0.f, t2 = 0.f;
#pragma unroll
        for (int i = 0; i < 8; i++) { t += redbuf[i]; t2 += redbuf[8 + i]; }
        stat[0] = t;
        stat[1] = t2;
    }
    __syncthreads();
    const float mu = stat[0] * (1.f / 768.f);
    const float var = stat[1] * (1.f / 768.f) - mu * mu;
    const float rstd = rsqrtf(var + 1e-5f);

#pragma unroll
    for (int i = 0; i < 3; i++) {
        int col = tid + i * 256;
        out[(size_t)dst * H + col] = (y[i] - mu) * rstd * gamma[col] + beta[col];
    }
}

// ---------------------------------------------------------------------------
extern "C" void kernel_launch(void* const* d_in, const int* in_sizes, int n_in,
                              void* d_out, int out_size) {
    const float* atom     = (const float*)d_in[0];
    const float* Wq       = (const float*)d_in[1];
    const float* bq       = (const float*)d_in[2];
    const float* Wk       = (const float*)d_in[3];
    const float* bk       = (const float*)d_in[4];
    const float* Wv       = (const float*)d_in[5];
    const float* bv       = (const float*)d_in[6];
    const float* Wo       = (const float*)d_in[7];
    const float* bo       = (const float*)d_in[8];
    const float* gamma    = (const float*)d_in[9];
    const float* beta     = (const float*)d_in[10];
    const int*   a_starts = (const int*)d_in[11];
    const int*   a_sizes  = (const int*)d_in[12];
    float* out = (float*)d_out;

    __half *pXh, *pCh, *pWh, *pP;
    float* pCf;
    cudaGetSymbolAddress((void**)&pXh, g_Xh);
    cudaGetSymbolAddress((void**)&pCh, g_Ch);
    cudaGetSymbolAddress((void**)&pWh, g_Wh);
    cudaGetSymbolAddress((void**)&pP, g_PRJ);
    cudaGetSymbolAddress((void**)&pCf, g_Cf);
    const size_t WSZ = (size_t)H * H;

    cudaFuncSetAttribute(attn_tc_kernel, cudaFuncAttributeMaxDynamicSharedMemorySize,
                         ATT_SMEM);
    cudaFuncSetAttribute(gemm_f16_kernel<true>,
                         cudaFuncAttributeMaxDynamicSharedMemorySize, GEMM_SMEM);
    cudaFuncSetAttribute(gemm_f16_kernel<false>,
                         cudaFuncAttributeMaxDynamicSharedMemorySize, GEMM_SMEM);

    build_x_kernel<<<(NROWS * H / 4) / 256, 256>>>(atom, a_starts, a_sizes);
    cvt_w_kernel<<<(4 * H * H / 4) / 256, 256>>>(Wq, Wk, Wv, Wo);

    // fused QKV: N = 2304
    dim3 qkvgrid(2304 / BN, NROWS / BM);    // (18, 256)
    gemm_f16_kernel<true><<<qkvgrid, 256, GEMM_SMEM>>>(
        pXh, pWh, bq, bk, bv, nullptr, pP, a_sizes);

    attn_tc_kernel<<<dim3(NH, MOLS), ATT_THREADS, ATT_SMEM>>>(a_sizes);

    dim3 ogrid(H / BN, NROWS / BM);         // (6, 256)
    gemm_f16_kernel<false><<<ogrid, 256, GEMM_SMEM>>>(
        pCh, pWh + 3 * WSZ, bo, nullptr, nullptr, pCf, nullptr, a_sizes);

    ln_kernel<<<NROWS, 256>>>(atom, gamma, beta, a_starts, a_sizes, out);
}